// round 1
// baseline (speedup 1.0000x reference)
#include <cuda_runtime.h>

// ---------------------------------------------------------------------------
// AgentAttention: b=32, c=384, h=w=56 (n=3136), heads=12, hd=32, agents=49
// ---------------------------------------------------------------------------
static constexpr int NB   = 32;
static constexpr int NC   = 384;
static constexpr int NH   = 12;
static constexpr int ND   = 32;     // head dim
static constexpr int NA   = 49;     // agent tokens
static constexpr int HW   = 56;
static constexpr int NPIX = HW * HW;      // 3136
static constexpr int NQKV = 3 * NC;       // 1152
static constexpr float SCALE = 0.17677669529663687f;  // 32^-0.5

// Scratch (device globals: no cudaMalloc allowed)
__device__ float g_qkv  [(size_t)NB * NPIX * NQKV];   // [b][n][3c]
__device__ float g_agent[(size_t)NB * NA * NC];       // [b][a][c]
__device__ float g_pb1  [(size_t)NH * NA * NPIX];     // [h][a][n]
__device__ float g_ab1  [(size_t)NH * NA * NPIX];     // [h][a][n]
__device__ float g_av   [(size_t)NB * NH * NA * ND];  // [b][h][a][d]
__device__ float g_o    [(size_t)NB * NPIX * NC];     // [b][n][c]
__device__ float g_oproj[(size_t)NB * NPIX * NC];     // [b][n][c]

// ---------------------------------------------------------------------------
// Generic tiled SGEMM body: C[m][n] = sum_k A(m,k) * W[k][n] + bias[n]
// BM=64, BN=128, BK=16, 128 threads, 8x8 per-thread tile.
// ATRANS=true : A stored row-major [M][K]   (lda = K)
// ATRANS=false: A stored K-major   [K][NPIX] (x layout, lda = NPIX)
// ---------------------------------------------------------------------------
template <bool ATRANS>
__device__ __forceinline__ void gemm_body(const float* __restrict__ Ab,
                                          const float* __restrict__ W,
                                          const float* __restrict__ bias,
                                          float* __restrict__ Cb,
                                          int K, int Nt)
{
    const int m0 = blockIdx.x * 64;
    const int n0 = blockIdx.y * 128;

    __shared__ float As[16 * 65];
    __shared__ float Bs[16 * 128];

    const int tid = threadIdx.x;
    const int tx  = tid & 15;    // 0..15  (n direction)
    const int ty  = tid >> 4;    // 0..7   (m direction)

    float acc[8][8];
#pragma unroll
    for (int i = 0; i < 8; i++)
#pragma unroll
        for (int j = 0; j < 8; j++) acc[i][j] = 0.f;

    for (int k0 = 0; k0 < K; k0 += 16) {
        if (ATRANS) {
#pragma unroll
            for (int j = 0; j < 8; j++) {
                int idx = tid + j * 128;            // 0..1023
                int m = idx >> 4, k = idx & 15;     // coalesced along k
                As[k * 65 + m] = Ab[(long)(m0 + m) * K + k0 + k];
            }
        } else {
#pragma unroll
            for (int j = 0; j < 8; j++) {
                int idx = tid + j * 128;
                int k = idx >> 6, m = idx & 63;     // coalesced along m
                As[k * 65 + m] = Ab[(long)(k0 + k) * NPIX + m0 + m];
            }
        }
#pragma unroll
        for (int j = 0; j < 16; j++) {
            int idx = tid + j * 128;                // 0..2047
            int k = idx >> 7, n = idx & 127;        // coalesced along n
            Bs[k * 128 + n] = W[(long)(k0 + k) * Nt + n0 + n];
        }
        __syncthreads();

#pragma unroll
        for (int k = 0; k < 16; k++) {
            float a[8], bb[8];
#pragma unroll
            for (int i = 0; i < 8; i++) a[i] = As[k * 65 + ty * 8 + i];
            float4 b0 = *(const float4*)&Bs[k * 128 + tx * 8];
            float4 b1 = *(const float4*)&Bs[k * 128 + tx * 8 + 4];
            bb[0] = b0.x; bb[1] = b0.y; bb[2] = b0.z; bb[3] = b0.w;
            bb[4] = b1.x; bb[5] = b1.y; bb[6] = b1.z; bb[7] = b1.w;
#pragma unroll
            for (int i = 0; i < 8; i++)
#pragma unroll
                for (int j = 0; j < 8; j++)
                    acc[i][j] += a[i] * bb[j];
        }
        __syncthreads();
    }

#pragma unroll
    for (int i = 0; i < 8; i++) {
        int m = m0 + ty * 8 + i;
#pragma unroll
        for (int j = 0; j < 8; j++) {
            int n = n0 + tx * 8 + j;
            Cb[(long)m * Nt + n] = acc[i][j] + bias[n];
        }
    }
}

// K1: qkv = xf @ qkv_w + qkv_b.  A(m,k) = x[b][k][m] (already K-major).
__global__ void qkv_gemm_kernel(const float* __restrict__ x,
                                const float* __restrict__ W,
                                const float* __restrict__ bias)
{
    const int b = blockIdx.z;
    gemm_body<false>(x + (long)b * NC * NPIX, W, bias,
                     g_qkv + (long)b * NPIX * NQKV, NC, NQKV);
}

// K7: oproj = o @ proj_w + proj_b.  A row-major [NPIX][NC].
__global__ void proj_gemm_kernel(const float* __restrict__ W,
                                 const float* __restrict__ bias)
{
    const int b = blockIdx.z;
    gemm_body<true>(g_o + (long)b * NPIX * NC, W, bias,
                    g_oproj + (long)b * NPIX * NC, NC, NC);
}

// ---------------------------------------------------------------------------
// K2: agent pooling — mean over uniform 8x8 windows of q.
// grid (49, 32), block 384 (ch)
// ---------------------------------------------------------------------------
__global__ void pool_kernel()
{
    const int ch = threadIdx.x;
    const int a  = blockIdx.x;
    const int b  = blockIdx.y;
    const int py = a / 7, px = a % 7;
    float s = 0.f;
#pragma unroll
    for (int i = 0; i < 8; i++)
#pragma unroll
        for (int j = 0; j < 8; j++) {
            int nn = (py * 8 + i) * HW + px * 8 + j;
            s += g_qkv[(long)(b * NPIX + nn) * NQKV + ch];
        }
    g_agent[(long)(b * NA + a) * NC + ch] = s * (1.f / 64.f);
}

// ---------------------------------------------------------------------------
// K3: bilinear upsample of the two (H, A, 7, 7) biases to (H, A, 56, 56).
// jax.image.resize('bilinear') semantics: half-pixel centers, boundary
// clamp + renormalize (== clamp sample to [0, 6] for the linear kernel).
// ---------------------------------------------------------------------------
__global__ void biasup_kernel(const float* __restrict__ an,
                              const float* __restrict__ na)
{
    int idx = blockIdx.x * 256 + threadIdx.x;   // < 12*49*3136
    int xy = idx % NPIX;
    int ha = idx / NPIX;                        // h*49 + a
    int y = xy / HW, x = xy % HW;

    float fy = (y + 0.5f) * 0.125f - 0.5f;
    fy = fminf(fmaxf(fy, 0.f), 6.f);
    int y0 = (int)fy; float wy = fy - (float)y0; int y1 = min(y0 + 1, 6);

    float fx = (x + 0.5f) * 0.125f - 0.5f;
    fx = fminf(fmaxf(fx, 0.f), 6.f);
    int x0 = (int)fx; float wx = fx - (float)x0; int x1 = min(x0 + 1, 6);

    const float* a4 = an + (long)ha * 49;   // [7][7] tile
    const float* n4 = na + (long)ha * 49;

    float va = (1.f - wy) * ((1.f - wx) * a4[y0 * 7 + x0] + wx * a4[y0 * 7 + x1])
             +        wy  * ((1.f - wx) * a4[y1 * 7 + x0] + wx * a4[y1 * 7 + x1]);
    float vn = (1.f - wy) * ((1.f - wx) * n4[y0 * 7 + x0] + wx * n4[y0 * 7 + x1])
             +        wy  * ((1.f - wx) * n4[y1 * 7 + x0] + wx * n4[y1 * 7 + x1]);

    g_pb1[idx] = va;
    g_ab1[idx] = vn;
}

// ---------------------------------------------------------------------------
// K4: stage 1 — agent_v[b,h,a,:] = softmax_n(scale*ah·k_n + pb1) @ V
// Streaming over n (no score buffer). Scores are tiny (|s| << 80) so plain
// exp without max-subtraction is numerically safe and exact in fp32 terms.
// grid (12, 32), block 256 (8 warps; warp w owns agents w, w+8, ...).
// ---------------------------------------------------------------------------
__global__ void stage1_kernel()
{
    const int h = blockIdx.x, b = blockIdx.y;
    const int tid  = threadIdx.x;
    const int warp = tid >> 5, lane = tid & 31;

    __shared__ float ah_s[NA * 32];
    __shared__ float Ks[64 * 33];
    __shared__ float Vs[64 * 33];

    for (int e = tid; e < NA * 32; e += 256) {
        int a = e >> 5, d = e & 31;
        ah_s[e] = g_agent[(long)(b * NA + a) * NC + h * 32 + d];
    }

    float l[7], acc[7];
#pragma unroll
    for (int j = 0; j < 7; j++) { l[j] = 0.f; acc[j] = 0.f; }
    __syncthreads();

    for (int n0 = 0; n0 < NPIX; n0 += 64) {
        for (int e = tid; e < 64 * 32; e += 256) {
            int i = e >> 5, d = e & 31;
            long base = (long)(b * NPIX + n0 + i) * NQKV + h * 32 + d;
            Ks[i * 33 + d] = g_qkv[base + 384];
            Vs[i * 33 + d] = g_qkv[base + 768];
        }
        __syncthreads();

#pragma unroll
        for (int j = 0; j < 7; j++) {
            int a = warp + j * 8;
            if (a < NA) {
                float s0 = 0.f, s1 = 0.f;
#pragma unroll
                for (int d = 0; d < 32; d++) {
                    float av = ah_s[a * 32 + d];
                    s0 += av * Ks[lane * 33 + d];
                    s1 += av * Ks[(lane + 32) * 33 + d];
                }
                const float* pb = &g_pb1[(long)(h * NA + a) * NPIX + n0];
                s0 = s0 * SCALE + pb[lane];
                s1 = s1 * SCALE + pb[32 + lane];
                float p0 = __expf(s0);
                float p1 = __expf(s1);
                float ps = p0 + p1;
#pragma unroll
                for (int o = 16; o > 0; o >>= 1)
                    ps += __shfl_xor_sync(0xffffffffu, ps, o);
                l[j] += ps;
                float ac = acc[j];
#pragma unroll
                for (int i = 0; i < 32; i++) {
                    float pi = __shfl_sync(0xffffffffu, p0, i);
                    ac += pi * Vs[i * 33 + lane];
                }
#pragma unroll
                for (int i = 0; i < 32; i++) {
                    float pi = __shfl_sync(0xffffffffu, p1, i);
                    ac += pi * Vs[(32 + i) * 33 + lane];
                }
                acc[j] = ac;
            }
        }
        __syncthreads();
    }

#pragma unroll
    for (int j = 0; j < 7; j++) {
        int a = warp + j * 8;
        if (a < NA)
            g_av[(long)((b * NH + h) * NA + a) * ND + lane] = acc[j] / l[j];
    }
}

// ---------------------------------------------------------------------------
// K5: stage 2 — o[b,n,h*32+d] = softmax_a(scale*q_n·ah_a + ab1) @ agent_v
// One thread per query row (row length only 49). No max-subtraction.
// grid (25, 12, 32), block 128.
// ---------------------------------------------------------------------------
__global__ void stage2_kernel()
{
    const int nn = blockIdx.x * 128 + threadIdx.x;
    const int h = blockIdx.y, b = blockIdx.z;

    __shared__ float ah_s[NA * 32];
    __shared__ float av_s[NA * 32];
    for (int e = threadIdx.x; e < NA * 32; e += 128) {
        int a = e >> 5, d = e & 31;
        ah_s[e] = g_agent[(long)(b * NA + a) * NC + h * 32 + d];
        av_s[e] = g_av[(long)((b * NH + h) * NA + a) * ND + d];
    }
    __syncthreads();
    if (nn >= NPIX) return;

    float q[32];
    const long qbase = (long)(b * NPIX + nn) * NQKV + h * 32;
#pragma unroll
    for (int d = 0; d < 32; d++) q[d] = g_qkv[qbase + d];

    float acc[32];
#pragma unroll
    for (int d = 0; d < 32; d++) acc[d] = 0.f;
    float l = 0.f;

    for (int a = 0; a < NA; a++) {
        float t = 0.f;
#pragma unroll
        for (int d = 0; d < 32; d++) t += q[d] * ah_s[a * 32 + d];
        t = t * SCALE + g_ab1[(long)(h * NA + a) * NPIX + nn];
        float p = __expf(t);
        l += p;
#pragma unroll
        for (int d = 0; d < 32; d++) acc[d] += p * av_s[a * 32 + d];
    }

    float inv = 1.f / l;
    const long obase = (long)(b * NPIX + nn) * NC + h * 32;
#pragma unroll
    for (int d = 0; d < 32; d++) g_o[obase + d] = acc[d] * inv;
}

// ---------------------------------------------------------------------------
// K6: depthwise 3x3 conv on v (zero pad), added into g_o.
// grid (3136, 32), block 384 (ch)
// ---------------------------------------------------------------------------
__global__ void dwc_kernel(const float* __restrict__ dwc_w,
                           const float* __restrict__ dwc_b)
{
    const int ch = threadIdx.x;
    const int nn = blockIdx.x;
    const int b  = blockIdx.y;
    const int y = nn / HW, x = nn % HW;

    float s = dwc_b[ch];
#pragma unroll
    for (int dy = -1; dy <= 1; dy++)
#pragma unroll
        for (int dx = -1; dx <= 1; dx++) {
            int yy = y + dy, xx = x + dx;
            if (yy >= 0 && yy < HW && xx >= 0 && xx < HW)
                s += g_qkv[(long)(b * NPIX + yy * HW + xx) * NQKV + 768 + ch]
                   * dwc_w[ch * 9 + (dy + 1) * 3 + (dx + 1)];
        }
    g_o[(long)(b * NPIX + nn) * NC + ch] += s;
}

// ---------------------------------------------------------------------------
// K8: out[b][ch][nn] = x[b][ch][nn] * sigmoid(oproj[b][nn][ch])
// 32x32 shared-memory transpose tiles. grid (98, 12, 32), block (32, 8)
// ---------------------------------------------------------------------------
__global__ void final_kernel(const float* __restrict__ x,
                             float* __restrict__ out)
{
    __shared__ float tile[32][33];
    const int b   = blockIdx.z;
    const int ch0 = blockIdx.y * 32;
    const int nn0 = blockIdx.x * 32;
    const int tx = threadIdx.x, ty = threadIdx.y;

#pragma unroll
    for (int k = 0; k < 4; k++) {
        int r = ty + k * 8;   // row within nn tile
        tile[r][tx] = g_oproj[(long)(b * NPIX + nn0 + r) * NC + ch0 + tx];
    }
    __syncthreads();
#pragma unroll
    for (int k = 0; k < 4; k++) {
        int r = ty + k * 8;   // row within ch tile
        long idx = ((long)b * NC + ch0 + r) * NPIX + nn0 + tx;
        float o = tile[tx][r];
        out[idx] = x[idx] * (1.f / (1.f + __expf(-o)));
    }
}

// ---------------------------------------------------------------------------
extern "C" void kernel_launch(void* const* d_in, const int* in_sizes, int n_in,
                              void* d_out, int out_size)
{
    (void)in_sizes; (void)n_in; (void)out_size;
    const float* x      = (const float*)d_in[0];
    const float* qkv_w  = (const float*)d_in[1];
    const float* qkv_b  = (const float*)d_in[2];
    const float* proj_w = (const float*)d_in[3];
    const float* proj_b = (const float*)d_in[4];
    const float* an_b   = (const float*)d_in[5];
    const float* na_b   = (const float*)d_in[6];
    const float* dwc_w  = (const float*)d_in[7];
    const float* dwc_b  = (const float*)d_in[8];
    float* out = (float*)d_out;

    // 1. qkv = xf @ qkv_w + qkv_b     (M=3136/b, N=1152, K=384)
    qkv_gemm_kernel<<<dim3(49, 9, 32), 128>>>(x, qkv_w, qkv_b);
    // 2. agent tokens (8x8 mean pool of q)
    pool_kernel<<<dim3(49, 32), 384>>>();
    // 3. bilinear bias upsample (batch-independent)
    biasup_kernel<<<7203, 256>>>(an_b, na_b);
    // 4. stage 1: agent attention over keys -> agent_v
    stage1_kernel<<<dim3(12, 32), 256>>>();
    // 5. stage 2: queries attend to agents -> g_o
    stage2_kernel<<<dim3(25, 12, 32), 128>>>();
    // 6. depthwise conv on v, accumulated into g_o
    dwc_kernel<<<dim3(3136, 32), 384>>>(dwc_w, dwc_b);
    // 7. proj GEMM                    (M=3136/b, N=384, K=384)
    proj_gemm_kernel<<<dim3(49, 3, 32), 128>>>(proj_w, proj_b);
    // 8. transpose + sigmoid gate
    final_kernel<<<dim3(98, 12, 32), dim3(32, 8)>>>(x, out);
}

// round 3
// speedup vs baseline: 1.6885x; 1.6885x over previous
#include <cuda_runtime.h>

// ---------------------------------------------------------------------------
// AgentAttention: b=32, c=384, h=w=56 (n=3136), heads=12, hd=32, agents=49
// R3: GEMMs via portable mma.sync tf32 (HMMA) + cp.async double buffering.
//     (tcgen05 PTX is rejected: harness ptxas targets sm_103, not sm_103a.)
// ---------------------------------------------------------------------------
static constexpr int NB   = 32;
static constexpr int NC   = 384;
static constexpr int NH   = 12;
static constexpr int ND   = 32;
static constexpr int NA   = 49;
static constexpr int HW   = 56;
static constexpr int NPIX = HW * HW;      // 3136
static constexpr int NQKV = 3 * NC;       // 1152
static constexpr float SCALE = 0.17677669529663687f;

// Scratch (device globals: no cudaMalloc allowed)
__device__ float g_qkv  [(size_t)NB * NPIX * NQKV];
__device__ float g_agent[(size_t)NB * NA * NC];
__device__ float g_pb1  [(size_t)NH * NA * NPIX];
__device__ float g_ab1  [(size_t)NH * NA * NPIX];
__device__ float g_av   [(size_t)NB * NH * NA * ND];
__device__ float g_o    [(size_t)NB * NPIX * NC];
__device__ float g_oproj[(size_t)NB * NPIX * NC];

// ============================ portable PTX helpers =========================
__device__ __forceinline__ unsigned smem_u32(const void* p) {
    unsigned a;
    asm("{ .reg .u64 t; cvta.to.shared.u64 t, %1; cvt.u32.u64 %0, t; }"
        : "=r"(a) : "l"(p));
    return a;
}
__device__ __forceinline__ void cp_async16(unsigned saddr, const void* gaddr,
                                           bool pred) {
    int bytes = pred ? 16 : 0;
    asm volatile("cp.async.cg.shared.global [%0], [%1], 16, %2;"
                 :: "r"(saddr), "l"(gaddr), "r"(bytes) : "memory");
}
#define CP_COMMIT() asm volatile("cp.async.commit_group;" ::: "memory")
#define CP_WAIT(N)  asm volatile("cp.async.wait_group %0;" :: "n"(N) : "memory")

__device__ __forceinline__ void mma_tf32(float& c0, float& c1, float& c2, float& c3,
                                         unsigned a0, unsigned a1, unsigned a2,
                                         unsigned a3, unsigned b0, unsigned b1) {
    asm volatile(
        "mma.sync.aligned.m16n8k8.row.col.f32.tf32.tf32.f32 "
        "{%0,%1,%2,%3}, {%4,%5,%6,%7}, {%8,%9}, {%0,%1,%2,%3};"
        : "+f"(c0), "+f"(c1), "+f"(c2), "+f"(c3)
        : "r"(a0), "r"(a1), "r"(a2), "r"(a3), "r"(b0), "r"(b1));
}

// ============================ tf32 mma GEMM ================================
// C[m][n] = sum_k A(m,k) * W[k][n] + bias[n], per batch (blockIdx.z).
// ATRANS=true : A row-major [M][384]          (proj; A = g_o)
// ATRANS=false: A K-major   [384][NPIX]       (qkv;  A = x)
// CTA tile 128x128x32, 256 thr / 8 warps (4m x 2n), warp tile 32x64.
static constexpr int AS_STRIDE_K = 136;  // As[k][m] rows (BK x BM), pad 8
static constexpr int AS_STRIDE_M = 36;   // As[m][k] rows (BM x BK), pad 4
static constexpr int BS_STRIDE   = 136;  // Bs[k][n]
static constexpr int AS_WORDS_K  = 32 * AS_STRIDE_K;   // 4352
static constexpr int AS_WORDS_M  = 128 * AS_STRIDE_M;  // 4608
static constexpr int BS_WORDS    = 32 * BS_STRIDE;     // 4352

template <bool ATRANS>
__global__ void __launch_bounds__(256, 2)
gemm_mma(const float* __restrict__ A, size_t strideA,
         const float* __restrict__ W, const float* __restrict__ bias,
         float* __restrict__ C, size_t strideC, int Nt)
{
    extern __shared__ float sm[];
    constexpr int AS_WORDS = ATRANS ? AS_WORDS_M : AS_WORDS_K;
    float* As[2] = { sm, sm + AS_WORDS };
    float* Bs[2] = { sm + 2 * AS_WORDS, sm + 2 * AS_WORDS + BS_WORDS };

    const int tid  = threadIdx.x;
    const int lane = tid & 31, wid = tid >> 5;
    const int wm = wid & 3, wn = wid >> 2;        // warp grid 4m x 2n
    const int grp = lane >> 2, qd = lane & 3;
    const int m0 = blockIdx.x * 128;
    const int n0 = blockIdx.y * 128;
    const float* Ab = A + (size_t)blockIdx.z * strideA;
    float* Cb = C + (size_t)blockIdx.z * strideC;

    // --- async tile loader for K-chunk ks (k0 = ks*32) ---
    auto load_tiles = [&](int ks, int buf) {
        const int k0 = ks * 32;
        const unsigned as_u = smem_u32(As[buf]);
        const unsigned bs_u = smem_u32(Bs[buf]);
        if (ATRANS) {
            // As[m][k]: thread -> row m = tid>>1, 16B chunks kc = (tid&1)+2j
            int m = tid >> 1;
            bool p = (m0 + m) < NPIX;
            const float* gp = Ab + (size_t)(m0 + m) * NC + k0;
#pragma unroll
            for (int j = 0; j < 4; j++) {
                int kc = (tid & 1) + j * 2;
                cp_async16(as_u + (m * AS_STRIDE_M + kc * 4) * 4, gp + kc * 4, p);
            }
        } else {
            // As[k][m]: thread -> row k = tid>>3, 16B chunks c = (tid&7)+8j
            int k = tid >> 3;
            const float* gp = Ab + (size_t)(k0 + k) * NPIX + m0;
#pragma unroll
            for (int j = 0; j < 4; j++) {
                int c = (tid & 7) + j * 8;
                bool p = (m0 + c * 4) < NPIX;   // NPIX % 4 == 0
                cp_async16(as_u + (k * AS_STRIDE_K + c * 4) * 4, gp + c * 4, p);
            }
        }
        {   // Bs[k][n]
            int k = tid >> 3;
            const float* gp = W + (size_t)(k0 + k) * Nt + n0;
#pragma unroll
            for (int j = 0; j < 4; j++) {
                int c = (tid & 7) + j * 8;
                cp_async16(bs_u + (k * BS_STRIDE + c * 4) * 4, gp + c * 4, true);
            }
        }
    };

    float c[2][8][4];
#pragma unroll
    for (int i = 0; i < 2; i++)
#pragma unroll
        for (int j = 0; j < 8; j++)
#pragma unroll
            for (int r = 0; r < 4; r++) c[i][j][r] = 0.f;

    load_tiles(0, 0);
    CP_COMMIT();

    for (int ks = 0; ks < 12; ks++) {
        const int buf = ks & 1;
        if (ks < 11) { load_tiles(ks + 1, buf ^ 1); CP_COMMIT(); CP_WAIT(1); }
        else         { CP_WAIT(0); }
        __syncthreads();

        const float* as = As[buf];
        const float* bs = Bs[buf];
        const int mb = wm * 32;
        const int nb = wn * 64;
#pragma unroll
        for (int kk = 0; kk < 32; kk += 8) {
            unsigned a[2][4];
#pragma unroll
            for (int mf = 0; mf < 2; mf++) {
                int mrow = mb + mf * 16 + grp;
                if (ATRANS) {
                    const float* p = as + mrow * AS_STRIDE_M + kk + qd;
                    a[mf][0] = __float_as_uint(p[0]);
                    a[mf][1] = __float_as_uint(p[8 * AS_STRIDE_M]);
                    a[mf][2] = __float_as_uint(p[4]);
                    a[mf][3] = __float_as_uint(p[8 * AS_STRIDE_M + 4]);
                } else {
                    const float* p = as + (kk + qd) * AS_STRIDE_K + mrow;
                    a[mf][0] = __float_as_uint(p[0]);
                    a[mf][1] = __float_as_uint(p[8]);
                    a[mf][2] = __float_as_uint(p[4 * AS_STRIDE_K]);
                    a[mf][3] = __float_as_uint(p[4 * AS_STRIDE_K + 8]);
                }
            }
#pragma unroll
            for (int nf = 0; nf < 8; nf++) {
                const float* p = bs + (kk + qd) * BS_STRIDE + nb + nf * 8 + grp;
                unsigned b0 = __float_as_uint(p[0]);
                unsigned b1 = __float_as_uint(p[4 * BS_STRIDE]);
#pragma unroll
                for (int mf = 0; mf < 2; mf++)
                    mma_tf32(c[mf][nf][0], c[mf][nf][1], c[mf][nf][2], c[mf][nf][3],
                             a[mf][0], a[mf][1], a[mf][2], a[mf][3], b0, b1);
            }
        }
        __syncthreads();
    }

    // --- epilogue: registers -> gmem with bias (float2 per fragment row) ---
    float2 brow[8];
#pragma unroll
    for (int nf = 0; nf < 8; nf++)
        brow[nf] = *(const float2*)(bias + n0 + wn * 64 + nf * 8 + qd * 2);

#pragma unroll
    for (int mf = 0; mf < 2; mf++) {
#pragma unroll
        for (int half = 0; half < 2; half++) {
            int m = m0 + wm * 32 + mf * 16 + grp + half * 8;
            if (m < NPIX) {
                float* cp = Cb + (size_t)m * Nt + n0 + wn * 64 + qd * 2;
#pragma unroll
                for (int nf = 0; nf < 8; nf++) {
                    float2 v;
                    v.x = c[mf][nf][half * 2 + 0] + brow[nf].x;
                    v.y = c[mf][nf][half * 2 + 1] + brow[nf].y;
                    *(float2*)(cp + nf * 8) = v;
                }
            }
        }
    }
}

static constexpr int SMEM_QKV  = (2 * AS_WORDS_K + 2 * BS_WORDS) * 4;  // 69632
static constexpr int SMEM_PROJ = (2 * AS_WORDS_M + 2 * BS_WORDS) * 4;  // 71680

// ---------------------------------------------------------------------------
// K2: agent pooling — mean over uniform 8x8 windows of q.
// ---------------------------------------------------------------------------
__global__ void pool_kernel()
{
    const int ch = threadIdx.x;
    const int a  = blockIdx.x;
    const int b  = blockIdx.y;
    const int py = a / 7, px = a % 7;
    float s = 0.f;
#pragma unroll
    for (int i = 0; i < 8; i++)
#pragma unroll
        for (int j = 0; j < 8; j++) {
            int nn = (py * 8 + i) * HW + px * 8 + j;
            s += g_qkv[(long)(b * NPIX + nn) * NQKV + ch];
        }
    g_agent[(long)(b * NA + a) * NC + ch] = s * (1.f / 64.f);
}

// ---------------------------------------------------------------------------
// K3: bilinear upsample of (H, A, 7, 7) biases to (H, A, 56, 56).
// ---------------------------------------------------------------------------
__global__ void biasup_kernel(const float* __restrict__ an,
                              const float* __restrict__ na)
{
    int idx = blockIdx.x * 256 + threadIdx.x;
    int xy = idx % NPIX;
    int ha = idx / NPIX;
    int y = xy / HW, x = xy % HW;

    float fy = (y + 0.5f) * 0.125f - 0.5f;
    fy = fminf(fmaxf(fy, 0.f), 6.f);
    int y0 = (int)fy; float wy = fy - (float)y0; int y1 = min(y0 + 1, 6);

    float fx = (x + 0.5f) * 0.125f - 0.5f;
    fx = fminf(fmaxf(fx, 0.f), 6.f);
    int x0 = (int)fx; float wx = fx - (float)x0; int x1 = min(x0 + 1, 6);

    const float* a4 = an + (long)ha * 49;
    const float* n4 = na + (long)ha * 49;

    float va = (1.f - wy) * ((1.f - wx) * a4[y0 * 7 + x0] + wx * a4[y0 * 7 + x1])
             +        wy  * ((1.f - wx) * a4[y1 * 7 + x0] + wx * a4[y1 * 7 + x1]);
    float vn = (1.f - wy) * ((1.f - wx) * n4[y0 * 7 + x0] + wx * n4[y0 * 7 + x1])
             +        wy  * ((1.f - wx) * n4[y1 * 7 + x0] + wx * n4[y1 * 7 + x1]);

    g_pb1[idx] = va;
    g_ab1[idx] = vn;
}

// ---------------------------------------------------------------------------
// K4: stage 1 — agent_v[b,h,a,:] = softmax_n(scale*ah·k_n + pb1) @ V
// ---------------------------------------------------------------------------
__global__ void stage1_kernel()
{
    const int h = blockIdx.x, b = blockIdx.y;
    const int tid  = threadIdx.x;
    const int warp = tid >> 5, lane = tid & 31;

    __shared__ float ah_s[NA * 32];
    __shared__ float Ks[64 * 33];
    __shared__ float Vs[64 * 33];

    for (int e = tid; e < NA * 32; e += 256) {
        int a = e >> 5, d = e & 31;
        ah_s[e] = g_agent[(long)(b * NA + a) * NC + h * 32 + d];
    }

    float l[7], acc[7];
#pragma unroll
    for (int j = 0; j < 7; j++) { l[j] = 0.f; acc[j] = 0.f; }
    __syncthreads();

    for (int n0 = 0; n0 < NPIX; n0 += 64) {
        for (int e = tid; e < 64 * 32; e += 256) {
            int i = e >> 5, d = e & 31;
            long base = (long)(b * NPIX + n0 + i) * NQKV + h * 32 + d;
            Ks[i * 33 + d] = g_qkv[base + 384];
            Vs[i * 33 + d] = g_qkv[base + 768];
        }
        __syncthreads();

#pragma unroll
        for (int j = 0; j < 7; j++) {
            int a = warp + j * 8;
            if (a < NA) {
                float s0 = 0.f, s1 = 0.f;
#pragma unroll
                for (int d = 0; d < 32; d++) {
                    float av = ah_s[a * 32 + d];
                    s0 += av * Ks[lane * 33 + d];
                    s1 += av * Ks[(lane + 32) * 33 + d];
                }
                const float* pb = &g_pb1[(long)(h * NA + a) * NPIX + n0];
                s0 = s0 * SCALE + pb[lane];
                s1 = s1 * SCALE + pb[32 + lane];
                float p0 = __expf(s0);
                float p1 = __expf(s1);
                float ps = p0 + p1;
#pragma unroll
                for (int o = 16; o > 0; o >>= 1)
                    ps += __shfl_xor_sync(0xffffffffu, ps, o);
                l[j] += ps;
                float ac = acc[j];
#pragma unroll
                for (int i = 0; i < 32; i++) {
                    float pi = __shfl_sync(0xffffffffu, p0, i);
                    ac += pi * Vs[i * 33 + lane];
                }
#pragma unroll
                for (int i = 0; i < 32; i++) {
                    float pi = __shfl_sync(0xffffffffu, p1, i);
                    ac += pi * Vs[(32 + i) * 33 + lane];
                }
                acc[j] = ac;
            }
        }
        __syncthreads();
    }

#pragma unroll
    for (int j = 0; j < 7; j++) {
        int a = warp + j * 8;
        if (a < NA)
            g_av[(long)((b * NH + h) * NA + a) * ND + lane] = acc[j] / l[j];
    }
}

// ---------------------------------------------------------------------------
// K5: stage 2 — o[b,n,h*32+d] = softmax_a(scale*q_n·ah_a + ab1) @ agent_v
// ---------------------------------------------------------------------------
__global__ void stage2_kernel()
{
    const int nn = blockIdx.x * 128 + threadIdx.x;
    const int h = blockIdx.y, b = blockIdx.z;

    __shared__ float ah_s[NA * 32];
    __shared__ float av_s[NA * 32];
    for (int e = threadIdx.x; e < NA * 32; e += 128) {
        int a = e >> 5, d = e & 31;
        ah_s[e] = g_agent[(long)(b * NA + a) * NC + h * 32 + d];
        av_s[e] = g_av[(long)((b * NH + h) * NA + a) * ND + d];
    }
    __syncthreads();
    if (nn >= NPIX) return;

    float q[32];
    const long qbase = (long)(b * NPIX + nn) * NQKV + h * 32;
#pragma unroll
    for (int d = 0; d < 32; d++) q[d] = g_qkv[qbase + d];

    float acc[32];
#pragma unroll
    for (int d = 0; d < 32; d++) acc[d] = 0.f;
    float l = 0.f;

    for (int a = 0; a < NA; a++) {
        float t = 0.f;
#pragma unroll
        for (int d = 0; d < 32; d++) t += q[d] * ah_s[a * 32 + d];
        t = t * SCALE + g_ab1[(long)(h * NA + a) * NPIX + nn];
        float p = __expf(t);
        l += p;
#pragma unroll
        for (int d = 0; d < 32; d++) acc[d] += p * av_s[a * 32 + d];
    }

    float inv = 1.f / l;
    const long obase = (long)(b * NPIX + nn) * NC + h * 32;
#pragma unroll
    for (int d = 0; d < 32; d++) g_o[obase + d] = acc[d] * inv;
}

// ---------------------------------------------------------------------------
// K6: depthwise 3x3 conv on v (zero pad), added into g_o.
// ---------------------------------------------------------------------------
__global__ void dwc_kernel(const float* __restrict__ dwc_w,
                           const float* __restrict__ dwc_b)
{
    const int ch = threadIdx.x;
    const int nn = blockIdx.x;
    const int b  = blockIdx.y;
    const int y = nn / HW, x = nn % HW;

    float s = dwc_b[ch];
#pragma unroll
    for (int dy = -1; dy <= 1; dy++)
#pragma unroll
        for (int dx = -1; dx <= 1; dx++) {
            int yy = y + dy, xx = x + dx;
            if (yy >= 0 && yy < HW && xx >= 0 && xx < HW)
                s += g_qkv[(long)(b * NPIX + yy * HW + xx) * NQKV + 768 + ch]
                   * dwc_w[ch * 9 + (dy + 1) * 3 + (dx + 1)];
        }
    g_o[(long)(b * NPIX + nn) * NC + ch] += s;
}

// ---------------------------------------------------------------------------
// K8: out[b][ch][nn] = x[b][ch][nn] * sigmoid(oproj[b][nn][ch])
// ---------------------------------------------------------------------------
__global__ void final_kernel(const float* __restrict__ x,
                             float* __restrict__ out)
{
    __shared__ float tile[32][33];
    const int b   = blockIdx.z;
    const int ch0 = blockIdx.y * 32;
    const int nn0 = blockIdx.x * 32;
    const int tx = threadIdx.x, ty = threadIdx.y;

#pragma unroll
    for (int k = 0; k < 4; k++) {
        int r = ty + k * 8;
        tile[r][tx] = g_oproj[(long)(b * NPIX + nn0 + r) * NC + ch0 + tx];
    }
    __syncthreads();
#pragma unroll
    for (int k = 0; k < 4; k++) {
        int r = ty + k * 8;
        long idx = ((long)b * NC + ch0 + r) * NPIX + nn0 + tx;
        float o = tile[tx][r];
        out[idx] = x[idx] * (1.f / (1.f + __expf(-o)));
    }
}

// ---------------------------------------------------------------------------
extern "C" void kernel_launch(void* const* d_in, const int* in_sizes, int n_in,
                              void* d_out, int out_size)
{
    (void)in_sizes; (void)n_in; (void)out_size;
    const float* x      = (const float*)d_in[0];
    const float* qkv_w  = (const float*)d_in[1];
    const float* qkv_b  = (const float*)d_in[2];
    const float* proj_w = (const float*)d_in[3];
    const float* proj_b = (const float*)d_in[4];
    const float* an_b   = (const float*)d_in[5];
    const float* na_b   = (const float*)d_in[6];
    const float* dwc_w  = (const float*)d_in[7];
    const float* dwc_b  = (const float*)d_in[8];
    float* out = (float*)d_out;

    cudaFuncSetAttribute(gemm_mma<false>,
                         cudaFuncAttributeMaxDynamicSharedMemorySize, SMEM_QKV);
    cudaFuncSetAttribute(gemm_mma<true>,
                         cudaFuncAttributeMaxDynamicSharedMemorySize, SMEM_PROJ);

    float* qkv_out;  cudaGetSymbolAddress((void**)&qkv_out,  g_qkv);
    float* o_in;     cudaGetSymbolAddress((void**)&o_in,     g_o);
    float* proj_out; cudaGetSymbolAddress((void**)&proj_out, g_oproj);

    // 1. qkv = xf @ qkv_w + qkv_b   (A = x, K-major per batch)
    gemm_mma<false><<<dim3(25, 9, 32), 256, SMEM_QKV>>>(
        x, (size_t)NC * NPIX, qkv_w, qkv_b, qkv_out, (size_t)NPIX * NQKV, NQKV);
    // 2. agent tokens (8x8 mean pool of q)
    pool_kernel<<<dim3(49, 32), 384>>>();
    // 3. bilinear bias upsample
    biasup_kernel<<<7203, 256>>>(an_b, na_b);
    // 4. stage 1
    stage1_kernel<<<dim3(12, 32), 256>>>();
    // 5. stage 2
    stage2_kernel<<<dim3(25, 12, 32), 128>>>();
    // 6. depthwise conv on v, accumulated into g_o
    dwc_kernel<<<dim3(3136, 32), 384>>>(dwc_w, dwc_b);
    // 7. oproj = o @ proj_w + proj_b  (A = g_o, row-major)
    gemm_mma<true><<<dim3(25, 3, 32), 256, SMEM_PROJ>>>(
        o_in, (size_t)NPIX * NC, proj_w, proj_b, proj_out, (size_t)NPIX * NC, NC);
    // 8. transpose + sigmoid gate
    final_kernel<<<dim3(98, 12, 32), dim3(32, 8)>>>(x, out);
}

// round 4
// speedup vs baseline: 2.0345x; 1.2049x over previous
#include <cuda_runtime.h>
#include <cuda_fp16.h>

// ---------------------------------------------------------------------------
// AgentAttention: b=32, c=384, h=w=56 (n=3136), heads=12, hd=32, agents=49
// R4: GEMMs via fp16 m16n8k16 mma.sync + ldmatrix (same 10-bit mantissa as
//     tf32, 2x MMA throughput, 3.6x fewer issue slots). stage2 q staged
//     through smem (kills uncoalesced stride-1152 gather).
// ---------------------------------------------------------------------------
static constexpr int NB   = 32;
static constexpr int NC   = 384;
static constexpr int NH   = 12;
static constexpr int ND   = 32;
static constexpr int NA   = 49;
static constexpr int HW   = 56;
static constexpr int NPIX = HW * HW;      // 3136
static constexpr int NQKV = 3 * NC;       // 1152
static constexpr float SCALE = 0.17677669529663687f;

// Scratch (device globals: no cudaMalloc allowed)
__device__ float  g_qkv  [(size_t)NB * NPIX * NQKV];
__device__ float  g_agent[(size_t)NB * NA * NC];
__device__ float  g_pb1  [(size_t)NH * NA * NPIX];
__device__ float  g_ab1  [(size_t)NH * NA * NPIX];
__device__ float  g_av   [(size_t)NB * NH * NA * ND];
__device__ float  g_o    [(size_t)NB * NPIX * NC];
__device__ float  g_oproj[(size_t)NB * NPIX * NC];
// fp16 operand buffers (padded for the ragged M edge: 25*128=3200 > 3136)
__device__ __half g_xh   [(size_t)NB * NC * NPIX + 128];
__device__ __half g_oh   [(size_t)NB * NPIX * NC + (size_t)64 * NC];
__device__ __half g_wqkvh[(size_t)NC * NQKV];
__device__ __half g_wprojh[(size_t)NC * NC];

// ============================ portable PTX helpers =========================
__device__ __forceinline__ unsigned smem_u32(const void* p) {
    unsigned a;
    asm("{ .reg .u64 t; cvta.to.shared.u64 t, %1; cvt.u32.u64 %0, t; }"
        : "=r"(a) : "l"(p));
    return a;
}
__device__ __forceinline__ void cp_async16(unsigned saddr, const void* gaddr) {
    asm volatile("cp.async.cg.shared.global [%0], [%1], 16;"
                 :: "r"(saddr), "l"(gaddr) : "memory");
}
#define CP_COMMIT() asm volatile("cp.async.commit_group;" ::: "memory")
#define CP_WAIT(N)  asm volatile("cp.async.wait_group %0;" :: "n"(N) : "memory")

__device__ __forceinline__ void ldmat4(unsigned* r, unsigned addr) {
    asm volatile("ldmatrix.sync.aligned.m8n8.x4.shared.b16 {%0,%1,%2,%3}, [%4];"
        : "=r"(r[0]), "=r"(r[1]), "=r"(r[2]), "=r"(r[3]) : "r"(addr));
}
__device__ __forceinline__ void ldmat4t(unsigned* r, unsigned addr) {
    asm volatile("ldmatrix.sync.aligned.m8n8.x4.trans.shared.b16 {%0,%1,%2,%3}, [%4];"
        : "=r"(r[0]), "=r"(r[1]), "=r"(r[2]), "=r"(r[3]) : "r"(addr));
}
__device__ __forceinline__ void mma_f16(float* c, const unsigned* a,
                                        unsigned b0, unsigned b1) {
    asm volatile(
        "mma.sync.aligned.m16n8k16.row.col.f32.f16.f16.f32 "
        "{%0,%1,%2,%3}, {%4,%5,%6,%7}, {%8,%9}, {%0,%1,%2,%3};"
        : "+f"(c[0]), "+f"(c[1]), "+f"(c[2]), "+f"(c[3])
        : "r"(a[0]), "r"(a[1]), "r"(a[2]), "r"(a[3]), "r"(b0), "r"(b1));
}

// ============================ fp16 mma GEMM ================================
// C[m][n] = sum_k A(m,k) * W[k][n] + bias[n], per batch (blockIdx.z).
// ATRANS=true : A row-major [M][384] fp16     (proj; A = g_oh)
// ATRANS=false: A K-major   [384][NPIX] fp16  (qkv;  A = g_xh)
// CTA tile 128x128x32, 256 thr / 8 warps (4m x 2n), warp tile 32x64.
static constexpr int AS_STR_K = 136;  // As[k][m] halves/row (128 + 8 pad)
static constexpr int AS_STR_M = 40;   // As[m][k] halves/row (32 + 8 pad)
static constexpr int BS_STR   = 136;  // Bs[k][n]

template <bool ATRANS>
__global__ void __launch_bounds__(256, 2)
gemm_h(const __half* __restrict__ A, size_t strideA,
       const __half* __restrict__ W, const float* __restrict__ bias,
       float* __restrict__ C, size_t strideC, int Nt)
{
    constexpr int AS_HALVES = ATRANS ? 128 * AS_STR_M : 32 * AS_STR_K;
    __shared__ __align__(16) __half As[2][AS_HALVES];
    __shared__ __align__(16) __half Bs[2][32 * BS_STR];

    const int tid  = threadIdx.x;
    const int lane = tid & 31, wid = tid >> 5;
    const int wm = wid & 3, wn = wid >> 2;        // warp grid 4m x 2n
    const int grp = lane >> 2, qd = lane & 3;
    const int g8 = lane >> 3, r8 = lane & 7;      // ldmatrix lane decode
    const int m0 = blockIdx.x * 128;
    const int n0 = blockIdx.y * 128;
    const __half* Ab = A + (size_t)blockIdx.z * strideA;
    float* Cb = C + (size_t)blockIdx.z * strideC;

    auto load_tiles = [&](int ks, int buf) {
        const int k0 = ks * 32;
        const unsigned as_u = smem_u32(As[buf]);
        const unsigned bs_u = smem_u32(Bs[buf]);
        if (ATRANS) {
            // As[m][k]: row m = tid>>1, 16B chunks c = (tid&1)+2j (32 halves/row)
            int m = tid >> 1;
            const __half* gp = Ab + (size_t)(m0 + m) * NC + k0;
#pragma unroll
            for (int j = 0; j < 2; j++) {
                int c = (tid & 1) + j * 2;
                cp_async16(as_u + (m * AS_STR_M + c * 8) * 2, gp + c * 8);
            }
        } else {
            // As[k][m]: row k = tid>>3, 16B chunks c = (tid&7)+8j (128 halves/row)
            int k = tid >> 3;
            const __half* gp = Ab + (size_t)(k0 + k) * NPIX + m0;
#pragma unroll
            for (int j = 0; j < 2; j++) {
                int c = (tid & 7) + j * 8;
                cp_async16(as_u + (k * AS_STR_K + c * 8) * 2, gp + c * 8);
            }
        }
        {   // Bs[k][n]: row k = tid>>3, chunks c = (tid&7)+8j
            int k = tid >> 3;
            const __half* gp = W + (size_t)(k0 + k) * Nt + n0;
#pragma unroll
            for (int j = 0; j < 2; j++) {
                int c = (tid & 7) + j * 8;
                cp_async16(bs_u + (k * BS_STR + c * 8) * 2, gp + c * 8);
            }
        }
    };

    float c[2][8][4];
#pragma unroll
    for (int i = 0; i < 2; i++)
#pragma unroll
        for (int j = 0; j < 8; j++)
#pragma unroll
            for (int r = 0; r < 4; r++) c[i][j][r] = 0.f;

    load_tiles(0, 0);
    CP_COMMIT();

    const int mb = wm * 32;
    const int nb = wn * 64;

    for (int ks = 0; ks < 12; ks++) {
        const int buf = ks & 1;
        if (ks < 11) { load_tiles(ks + 1, buf ^ 1); CP_COMMIT(); CP_WAIT(1); }
        else         { CP_WAIT(0); }
        __syncthreads();

        const unsigned as_u = smem_u32(As[buf]);
        const unsigned bs_u = smem_u32(Bs[buf]);

#pragma unroll
        for (int kk = 0; kk < 32; kk += 16) {
            unsigned a[2][4];
#pragma unroll
            for (int mf = 0; mf < 2; mf++) {
                if (ATRANS) {
                    // non-trans from [m][k]: rows m, (g&1)->m+8, (g>>1)->k+8
                    unsigned ah = (mb + mf * 16 + (g8 & 1) * 8 + r8) * AS_STR_M
                                + kk + (g8 >> 1) * 8;
                    ldmat4(a[mf], as_u + ah * 2);
                } else {
                    // trans from [k][m]: rows k, (g&1)->m+8, (g>>1)->k+8
                    unsigned ah = (kk + (g8 >> 1) * 8 + r8) * AS_STR_K
                                + mb + mf * 16 + (g8 & 1) * 8;
                    ldmat4t(a[mf], as_u + ah * 2);
                }
            }
#pragma unroll
            for (int ng = 0; ng < 4; ng++) {
                // B trans from [k][n]: rows k, (g&1)->k+8, (g>>1)->n+8
                unsigned bh = (kk + (g8 & 1) * 8 + r8) * BS_STR
                            + nb + ng * 16 + (g8 >> 1) * 8;
                unsigned b[4];
                ldmat4t(b, bs_u + bh * 2);
#pragma unroll
                for (int mf = 0; mf < 2; mf++) {
                    mma_f16(c[mf][ng * 2 + 0], a[mf], b[0], b[1]);
                    mma_f16(c[mf][ng * 2 + 1], a[mf], b[2], b[3]);
                }
            }
        }
        __syncthreads();
    }

    // --- epilogue: registers -> gmem with bias ---
    float2 brow[8];
#pragma unroll
    for (int nf = 0; nf < 8; nf++)
        brow[nf] = *(const float2*)(bias + n0 + nb + nf * 8 + qd * 2);

#pragma unroll
    for (int mf = 0; mf < 2; mf++) {
#pragma unroll
        for (int half = 0; half < 2; half++) {
            int m = m0 + mb + mf * 16 + grp + half * 8;
            if (m < NPIX) {
                float* cp = Cb + (size_t)m * Nt + n0 + nb + qd * 2;
#pragma unroll
                for (int nf = 0; nf < 8; nf++) {
                    float2 v;
                    v.x = c[mf][nf][half * 2 + 0] + brow[nf].x;
                    v.y = c[mf][nf][half * 2 + 1] + brow[nf].y;
                    *(float2*)(cp + nf * 8) = v;
                }
            }
        }
    }
}

// ---------------------------------------------------------------------------
// K0: fp32 -> fp16 conversion (round-to-nearest; error 2^-11 ~= tf32)
// ---------------------------------------------------------------------------
__global__ void f2h_kernel(const float4* __restrict__ src,
                           __half2* __restrict__ dst, long n4)
{
    long i = (long)blockIdx.x * blockDim.x + threadIdx.x;
    long stride = (long)gridDim.x * blockDim.x;
    for (; i < n4; i += stride) {
        float4 v = src[i];
        dst[2 * i]     = __floats2half2_rn(v.x, v.y);
        dst[2 * i + 1] = __floats2half2_rn(v.z, v.w);
    }
}

// ---------------------------------------------------------------------------
// K2: agent pooling — mean over uniform 8x8 windows of q.
// ---------------------------------------------------------------------------
__global__ void pool_kernel()
{
    const int ch = threadIdx.x;
    const int a  = blockIdx.x;
    const int b  = blockIdx.y;
    const int py = a / 7, px = a % 7;
    float s = 0.f;
#pragma unroll
    for (int i = 0; i < 8; i++)
#pragma unroll
        for (int j = 0; j < 8; j++) {
            int nn = (py * 8 + i) * HW + px * 8 + j;
            s += g_qkv[(long)(b * NPIX + nn) * NQKV + ch];
        }
    g_agent[(long)(b * NA + a) * NC + ch] = s * (1.f / 64.f);
}

// ---------------------------------------------------------------------------
// K3: bilinear upsample of (H, A, 7, 7) biases to (H, A, 56, 56).
// ---------------------------------------------------------------------------
__global__ void biasup_kernel(const float* __restrict__ an,
                              const float* __restrict__ na)
{
    int idx = blockIdx.x * 256 + threadIdx.x;
    int xy = idx % NPIX;
    int ha = idx / NPIX;
    int y = xy / HW, x = xy % HW;

    float fy = (y + 0.5f) * 0.125f - 0.5f;
    fy = fminf(fmaxf(fy, 0.f), 6.f);
    int y0 = (int)fy; float wy = fy - (float)y0; int y1 = min(y0 + 1, 6);

    float fx = (x + 0.5f) * 0.125f - 0.5f;
    fx = fminf(fmaxf(fx, 0.f), 6.f);
    int x0 = (int)fx; float wx = fx - (float)x0; int x1 = min(x0 + 1, 6);

    const float* a4 = an + (long)ha * 49;
    const float* n4 = na + (long)ha * 49;

    float va = (1.f - wy) * ((1.f - wx) * a4[y0 * 7 + x0] + wx * a4[y0 * 7 + x1])
             +        wy  * ((1.f - wx) * a4[y1 * 7 + x0] + wx * a4[y1 * 7 + x1]);
    float vn = (1.f - wy) * ((1.f - wx) * n4[y0 * 7 + x0] + wx * n4[y0 * 7 + x1])
             +        wy  * ((1.f - wx) * n4[y1 * 7 + x0] + wx * n4[y1 * 7 + x1]);

    g_pb1[idx] = va;
    g_ab1[idx] = vn;
}

// ---------------------------------------------------------------------------
// K4: stage 1 — agent_v[b,h,a,:] = softmax_n(scale*ah·k_n + pb1) @ V
// ---------------------------------------------------------------------------
__global__ void stage1_kernel()
{
    const int h = blockIdx.x, b = blockIdx.y;
    const int tid  = threadIdx.x;
    const int warp = tid >> 5, lane = tid & 31;

    __shared__ float ah_s[NA * 32];
    __shared__ float Ks[64 * 33];
    __shared__ float Vs[64 * 33];

    for (int e = tid; e < NA * 32; e += 256) {
        int a = e >> 5, d = e & 31;
        ah_s[e] = g_agent[(long)(b * NA + a) * NC + h * 32 + d];
    }

    float l[7], acc[7];
#pragma unroll
    for (int j = 0; j < 7; j++) { l[j] = 0.f; acc[j] = 0.f; }
    __syncthreads();

    for (int n0 = 0; n0 < NPIX; n0 += 64) {
        for (int e = tid; e < 64 * 32; e += 256) {
            int i = e >> 5, d = e & 31;
            long base = (long)(b * NPIX + n0 + i) * NQKV + h * 32 + d;
            Ks[i * 33 + d] = g_qkv[base + 384];
            Vs[i * 33 + d] = g_qkv[base + 768];
        }
        __syncthreads();

#pragma unroll
        for (int j = 0; j < 7; j++) {
            int a = warp + j * 8;
            if (a < NA) {
                float s0 = 0.f, s1 = 0.f;
#pragma unroll
                for (int d = 0; d < 32; d++) {
                    float av = ah_s[a * 32 + d];
                    s0 += av * Ks[lane * 33 + d];
                    s1 += av * Ks[(lane + 32) * 33 + d];
                }
                const float* pb = &g_pb1[(long)(h * NA + a) * NPIX + n0];
                s0 = s0 * SCALE + pb[lane];
                s1 = s1 * SCALE + pb[32 + lane];
                float p0 = __expf(s0);
                float p1 = __expf(s1);
                float ps = p0 + p1;
#pragma unroll
                for (int o = 16; o > 0; o >>= 1)
                    ps += __shfl_xor_sync(0xffffffffu, ps, o);
                l[j] += ps;
                float ac = acc[j];
#pragma unroll
                for (int i = 0; i < 32; i++) {
                    float pi = __shfl_sync(0xffffffffu, p0, i);
                    ac += pi * Vs[i * 33 + lane];
                }
#pragma unroll
                for (int i = 0; i < 32; i++) {
                    float pi = __shfl_sync(0xffffffffu, p1, i);
                    ac += pi * Vs[(32 + i) * 33 + lane];
                }
                acc[j] = ac;
            }
        }
        __syncthreads();
    }

#pragma unroll
    for (int j = 0; j < 7; j++) {
        int a = warp + j * 8;
        if (a < NA)
            g_av[(long)((b * NH + h) * NA + a) * ND + lane] = acc[j] / l[j];
    }
}

// ---------------------------------------------------------------------------
// K5: stage 2 — o[b,n,h*32+d] = softmax_a(scale*q_n·ah_a + ab1) @ agent_v
// q staged through smem (coalesced) to avoid stride-1152 gather.
// ---------------------------------------------------------------------------
__global__ void stage2_kernel()
{
    const int tid = threadIdx.x;
    const int nn0 = blockIdx.x * 128;
    const int h = blockIdx.y, b = blockIdx.z;

    __shared__ float ah_s[NA * 32];
    __shared__ float av_s[NA * 32];
    __shared__ float q_s[128 * 33];

    for (int e = tid; e < NA * 32; e += 128) {
        int a = e >> 5, d = e & 31;
        ah_s[e] = g_agent[(long)(b * NA + a) * NC + h * 32 + d];
        av_s[e] = g_av[(long)((b * NH + h) * NA + a) * ND + d];
    }
    for (int e = tid; e < 128 * 32; e += 128) {
        int row = e >> 5, d = e & 31;
        q_s[row * 33 + d] =
            g_qkv[(long)(b * NPIX + nn0 + row) * NQKV + h * 32 + d];
    }
    __syncthreads();

    const int nn = nn0 + tid;
    float q[32];
#pragma unroll
    for (int d = 0; d < 32; d++) q[d] = q_s[tid * 33 + d];

    float acc[32];
#pragma unroll
    for (int d = 0; d < 32; d++) acc[d] = 0.f;
    float l = 0.f;

    for (int a = 0; a < NA; a++) {
        float t = 0.f;
#pragma unroll
        for (int d = 0; d < 32; d++) t += q[d] * ah_s[a * 32 + d];
        t = t * SCALE + g_ab1[(long)(h * NA + a) * NPIX + nn];
        float p = __expf(t);
        l += p;
#pragma unroll
        for (int d = 0; d < 32; d++) acc[d] += p * av_s[a * 32 + d];
    }

    float inv = 1.f / l;
    const long obase = (long)(b * NPIX + nn) * NC + h * 32;
#pragma unroll
    for (int d = 0; d < 32; d++) g_o[obase + d] = acc[d] * inv;
}

// ---------------------------------------------------------------------------
// K6: depthwise 3x3 conv on v (zero pad), adds g_o, writes fp16 g_oh.
// ---------------------------------------------------------------------------
__global__ void dwc_kernel(const float* __restrict__ dwc_w,
                           const float* __restrict__ dwc_b)
{
    const int ch = threadIdx.x;
    const int nn = blockIdx.x;
    const int b  = blockIdx.y;
    const int y = nn / HW, x = nn % HW;

    float s = dwc_b[ch];
#pragma unroll
    for (int dy = -1; dy <= 1; dy++)
#pragma unroll
        for (int dx = -1; dx <= 1; dx++) {
            int yy = y + dy, xx = x + dx;
            if (yy >= 0 && yy < HW && xx >= 0 && xx < HW)
                s += g_qkv[(long)(b * NPIX + yy * HW + xx) * NQKV + 768 + ch]
                   * dwc_w[ch * 9 + (dy + 1) * 3 + (dx + 1)];
        }
    long idx = (long)(b * NPIX + nn) * NC + ch;
    g_oh[idx] = __float2half_rn(g_o[idx] + s);
}

// ---------------------------------------------------------------------------
// K8: out[b][ch][nn] = x[b][ch][nn] * sigmoid(oproj[b][nn][ch])
// ---------------------------------------------------------------------------
__global__ void final_kernel(const float* __restrict__ x,
                             float* __restrict__ out)
{
    __shared__ float tile[32][33];
    const int b   = blockIdx.z;
    const int ch0 = blockIdx.y * 32;
    const int nn0 = blockIdx.x * 32;
    const int tx = threadIdx.x, ty = threadIdx.y;

#pragma unroll
    for (int k = 0; k < 4; k++) {
        int r = ty + k * 8;
        tile[r][tx] = g_oproj[(long)(b * NPIX + nn0 + r) * NC + ch0 + tx];
    }
    __syncthreads();
#pragma unroll
    for (int k = 0; k < 4; k++) {
        int r = ty + k * 8;
        long idx = ((long)b * NC + ch0 + r) * NPIX + nn0 + tx;
        float o = tile[tx][r];
        out[idx] = x[idx] * (1.f / (1.f + __expf(-o)));
    }
}

// ---------------------------------------------------------------------------
extern "C" void kernel_launch(void* const* d_in, const int* in_sizes, int n_in,
                              void* d_out, int out_size)
{
    (void)in_sizes; (void)n_in; (void)out_size;
    const float* x      = (const float*)d_in[0];
    const float* qkv_w  = (const float*)d_in[1];
    const float* qkv_b  = (const float*)d_in[2];
    const float* proj_w = (const float*)d_in[3];
    const float* proj_b = (const float*)d_in[4];
    const float* an_b   = (const float*)d_in[5];
    const float* na_b   = (const float*)d_in[6];
    const float* dwc_w  = (const float*)d_in[7];
    const float* dwc_b  = (const float*)d_in[8];
    float* out = (float*)d_out;

    float* qkv_out;  cudaGetSymbolAddress((void**)&qkv_out,  g_qkv);
    float* proj_out; cudaGetSymbolAddress((void**)&proj_out, g_oproj);
    __half* xh;      cudaGetSymbolAddress((void**)&xh,       g_xh);
    __half* oh;      cudaGetSymbolAddress((void**)&oh,       g_oh);
    __half* wqkvh;   cudaGetSymbolAddress((void**)&wqkvh,    g_wqkvh);
    __half* wprojh;  cudaGetSymbolAddress((void**)&wprojh,   g_wprojh);

    // 0. fp32 -> fp16 conversions (x and weights)
    f2h_kernel<<<2048, 256>>>((const float4*)x, (__half2*)xh,
                              (long)NB * NC * NPIX / 4);
    f2h_kernel<<<128, 256>>>((const float4*)qkv_w, (__half2*)wqkvh,
                             (long)NC * NQKV / 4);
    f2h_kernel<<<64, 256>>>((const float4*)proj_w, (__half2*)wprojh,
                            (long)NC * NC / 4);

    // 1. qkv = xf @ qkv_w + qkv_b   (A = g_xh, K-major per batch)
    gemm_h<false><<<dim3(25, 9, 32), 256>>>(
        xh, (size_t)NC * NPIX, wqkvh, qkv_b, qkv_out,
        (size_t)NPIX * NQKV, NQKV);
    // 2. agent tokens (8x8 mean pool of q)
    pool_kernel<<<dim3(49, 32), 384>>>();
    // 3. bilinear bias upsample
    biasup_kernel<<<7203, 256>>>(an_b, na_b);
    // 4. stage 1
    stage1_kernel<<<dim3(12, 32), 256>>>();
    // 5. stage 2
    stage2_kernel<<<dim3(25, 12, 32), 128>>>();
    // 6. depthwise conv on v, adds g_o, emits fp16 g_oh
    dwc_kernel<<<dim3(3136, 32), 384>>>(dwc_w, dwc_b);
    // 7. oproj = o @ proj_w + proj_b  (A = g_oh, row-major)
    gemm_h<true><<<dim3(25, 3, 32), 256>>>(
        oh, (size_t)NPIX * NC, wprojh, proj_b, proj_out,
        (size_t)NPIX * NC, NC);
    // 8. transpose + sigmoid gate
    final_kernel<<<dim3(98, 12, 32), dim3(32, 8)>>>(x, out);
}

// round 5
// speedup vs baseline: 4.8702x; 2.3938x over previous
#include <cuda_runtime.h>
#include <cuda_fp16.h>

// ---------------------------------------------------------------------------
// AgentAttention: b=32, c=384, h=w=56 (n=3136), heads=12, hd=32, agents=49
// R5: everything on mma.sync fp16 — qkv GEMM writes head-split fp16 q/k/v,
//     stage1/stage2 are flash-style mma kernels with register P-passing,
//     ab1 pre-transposed, fp32 qkv scratch eliminated.
// ---------------------------------------------------------------------------
static constexpr int NB   = 32;
static constexpr int NC   = 384;
static constexpr int NH   = 12;
static constexpr int NA   = 49;
static constexpr int HW   = 56;
static constexpr int NPIX = HW * HW;      // 3136
static constexpr int NQKV = 3 * NC;       // 1152
static constexpr float SCALE = 0.17677669529663687f;

// Scratch (device globals: zero-initialized, no cudaMalloc allowed)
__device__ __half g_qh [(size_t)NB * NH * NPIX * 32 + 64 * 32];
__device__ __half g_kh [(size_t)NB * NH * NPIX * 32 + 64 * 32];
__device__ __half g_vh [(size_t)NB * NH * NPIX * 32 + 64 * 32];
__device__ __half g_agenth[(size_t)NB * NH * 64 * 32];   // rows 49..63 stay 0
__device__ __half g_avh   [(size_t)NB * NH * 64 * 32];
__device__ float  g_pb1 [(size_t)(NH * NA + 16) * NPIX];  // padded for a<64 reads
__device__ float  g_ab1t[(size_t)NH * NPIX * 64 + 64 * 64];  // [h][n][64], -inf pad
__device__ __half g_oh  [(size_t)NB * NPIX * NC + 64 * NC];
__device__ float  g_oproj[(size_t)NB * NPIX * NC];
__device__ __half g_xh  [(size_t)NB * NC * NPIX + 128];
__device__ __half g_wqkvh [(size_t)NC * NQKV];
__device__ __half g_wprojh[(size_t)NC * NC];

// ============================ portable PTX helpers =========================
__device__ __forceinline__ unsigned smem_u32(const void* p) {
    unsigned a;
    asm("{ .reg .u64 t; cvta.to.shared.u64 t, %1; cvt.u32.u64 %0, t; }"
        : "=r"(a) : "l"(p));
    return a;
}
__device__ __forceinline__ void cp_async16(unsigned saddr, const void* gaddr) {
    asm volatile("cp.async.cg.shared.global [%0], [%1], 16;"
                 :: "r"(saddr), "l"(gaddr) : "memory");
}
#define CP_COMMIT() asm volatile("cp.async.commit_group;" ::: "memory")
#define CP_WAIT(N)  asm volatile("cp.async.wait_group %0;" :: "n"(N) : "memory")

__device__ __forceinline__ void ldmat4(unsigned* r, unsigned addr) {
    asm volatile("ldmatrix.sync.aligned.m8n8.x4.shared.b16 {%0,%1,%2,%3}, [%4];"
        : "=r"(r[0]), "=r"(r[1]), "=r"(r[2]), "=r"(r[3]) : "r"(addr));
}
__device__ __forceinline__ void ldmat4t(unsigned* r, unsigned addr) {
    asm volatile("ldmatrix.sync.aligned.m8n8.x4.trans.shared.b16 {%0,%1,%2,%3}, [%4];"
        : "=r"(r[0]), "=r"(r[1]), "=r"(r[2]), "=r"(r[3]) : "r"(addr));
}
__device__ __forceinline__ void mma_f16(float* c, const unsigned* a,
                                        unsigned b0, unsigned b1) {
    asm volatile(
        "mma.sync.aligned.m16n8k16.row.col.f32.f16.f16.f32 "
        "{%0,%1,%2,%3}, {%4,%5,%6,%7}, {%8,%9}, {%0,%1,%2,%3};"
        : "+f"(c[0]), "+f"(c[1]), "+f"(c[2]), "+f"(c[3])
        : "r"(a[0]), "r"(a[1]), "r"(a[2]), "r"(a[3]), "r"(b0), "r"(b1));
}
__device__ __forceinline__ unsigned h2u(float x, float y) {
    __half2 h = __floats2half2_rn(x, y);
    return *(unsigned*)&h;
}

// ============================ qkv GEMM (fp16 head-split epilogue) ==========
// qkv = xf @ qkv_w + qkv_b ; A = g_xh K-major [384][NPIX] per batch.
// CTA 128x128x32, 256 thr / 8 warps (4m x 2n).
static constexpr int AS_STR_K = 136;
static constexpr int AS_STR_M = 40;
static constexpr int BS_STR   = 136;

__global__ void __launch_bounds__(256, 2)
gemm_qkv(const __half* __restrict__ A, const __half* __restrict__ W,
         const float* __restrict__ bias)
{
    __shared__ __align__(16) __half As[2][32 * AS_STR_K];
    __shared__ __align__(16) __half Bs[2][32 * BS_STR];

    const int tid  = threadIdx.x;
    const int lane = tid & 31, wid = tid >> 5;
    const int wm = wid & 3, wn = wid >> 2;
    const int grp = lane >> 2, qd = lane & 3;
    const int g8 = lane >> 3, r8 = lane & 7;
    const int m0 = blockIdx.x * 128;
    const int n0 = blockIdx.y * 128;
    const int b  = blockIdx.z;
    const __half* Ab = A + (size_t)b * NC * NPIX;

    auto load_tiles = [&](int ks, int buf) {
        const int k0 = ks * 32;
        const unsigned as_u = smem_u32(As[buf]);
        const unsigned bs_u = smem_u32(Bs[buf]);
        int k = tid >> 3;
        const __half* gp = Ab + (size_t)(k0 + k) * NPIX + m0;
        const __half* wp = W + (size_t)(k0 + k) * NQKV + n0;
#pragma unroll
        for (int j = 0; j < 2; j++) {
            int c = (tid & 7) + j * 8;
            cp_async16(as_u + (k * AS_STR_K + c * 8) * 2, gp + c * 8);
            cp_async16(bs_u + (k * BS_STR + c * 8) * 2, wp + c * 8);
        }
    };

    float c[2][8][4];
#pragma unroll
    for (int i = 0; i < 2; i++)
#pragma unroll
        for (int j = 0; j < 8; j++)
#pragma unroll
            for (int r = 0; r < 4; r++) c[i][j][r] = 0.f;

    load_tiles(0, 0);
    CP_COMMIT();
    const int mb = wm * 32, nb = wn * 64;

    for (int ks = 0; ks < 12; ks++) {
        const int buf = ks & 1;
        if (ks < 11) { load_tiles(ks + 1, buf ^ 1); CP_COMMIT(); CP_WAIT(1); }
        else         { CP_WAIT(0); }
        __syncthreads();
        const unsigned as_u = smem_u32(As[buf]);
        const unsigned bs_u = smem_u32(Bs[buf]);
#pragma unroll
        for (int kk = 0; kk < 32; kk += 16) {
            unsigned a[2][4];
#pragma unroll
            for (int mf = 0; mf < 2; mf++) {
                unsigned ah = (kk + (g8 >> 1) * 8 + r8) * AS_STR_K
                            + mb + mf * 16 + (g8 & 1) * 8;
                ldmat4t(a[mf], as_u + ah * 2);
            }
#pragma unroll
            for (int ng = 0; ng < 4; ng++) {
                unsigned bh = (kk + (g8 & 1) * 8 + r8) * BS_STR
                            + nb + ng * 16 + (g8 >> 1) * 8;
                unsigned bq[4];
                ldmat4t(bq, bs_u + bh * 2);
#pragma unroll
                for (int mf = 0; mf < 2; mf++) {
                    mma_f16(c[mf][ng * 2 + 0], a[mf], bq[0], bq[1]);
                    mma_f16(c[mf][ng * 2 + 1], a[mf], bq[2], bq[3]);
                }
            }
        }
        __syncthreads();
    }

    // epilogue: bias + fp16, head-split write to q/k/v [b][h][n][32]
    const int t = n0 / 384;
    __half* dst = (t == 0) ? g_qh : (t == 1) ? g_kh : g_vh;
    float2 brow[8];
#pragma unroll
    for (int nf = 0; nf < 8; nf++)
        brow[nf] = *(const float2*)(bias + n0 + nb + nf * 8 + qd * 2);

#pragma unroll
    for (int mf = 0; mf < 2; mf++) {
#pragma unroll
        for (int half = 0; half < 2; half++) {
            int m = m0 + mb + mf * 16 + grp + half * 8;
            if (m < NPIX) {
#pragma unroll
                for (int nf = 0; nf < 8; nf++) {
                    int nn = n0 + nb + nf * 8 + qd * 2;
                    int hh = (nn >> 5) % 12;
                    int d  = nn & 31;
                    float vx = c[mf][nf][half * 2 + 0] + brow[nf].x;
                    float vy = c[mf][nf][half * 2 + 1] + brow[nf].y;
                    *(__half2*)&dst[(((size_t)b * NH + hh) * NPIX + m) * 32 + d] =
                        __floats2half2_rn(vx, vy);
                }
            }
        }
    }
}

// ============================ proj GEMM (fp32 epilogue) ====================
__global__ void __launch_bounds__(256, 2)
gemm_proj(const __half* __restrict__ A, const __half* __restrict__ W,
          const float* __restrict__ bias, float* __restrict__ C)
{
    __shared__ __align__(16) __half As[2][128 * AS_STR_M];
    __shared__ __align__(16) __half Bs[2][32 * BS_STR];

    const int tid  = threadIdx.x;
    const int lane = tid & 31, wid = tid >> 5;
    const int wm = wid & 3, wn = wid >> 2;
    const int grp = lane >> 2, qd = lane & 3;
    const int g8 = lane >> 3, r8 = lane & 7;
    const int m0 = blockIdx.x * 128;
    const int n0 = blockIdx.y * 128;
    const __half* Ab = A + (size_t)blockIdx.z * NPIX * NC;
    float* Cb = C + (size_t)blockIdx.z * NPIX * NC;

    auto load_tiles = [&](int ks, int buf) {
        const int k0 = ks * 32;
        const unsigned as_u = smem_u32(As[buf]);
        const unsigned bs_u = smem_u32(Bs[buf]);
        {
            int m = tid >> 1;
            const __half* gp = Ab + (size_t)(m0 + m) * NC + k0;
#pragma unroll
            for (int j = 0; j < 2; j++) {
                int cc = (tid & 1) + j * 2;
                cp_async16(as_u + (m * AS_STR_M + cc * 8) * 2, gp + cc * 8);
            }
        }
        {
            int k = tid >> 3;
            const __half* wp = W + (size_t)(k0 + k) * NC + n0;
#pragma unroll
            for (int j = 0; j < 2; j++) {
                int cc = (tid & 7) + j * 8;
                cp_async16(bs_u + (k * BS_STR + cc * 8) * 2, wp + cc * 8);
            }
        }
    };

    float c[2][8][4];
#pragma unroll
    for (int i = 0; i < 2; i++)
#pragma unroll
        for (int j = 0; j < 8; j++)
#pragma unroll
            for (int r = 0; r < 4; r++) c[i][j][r] = 0.f;

    load_tiles(0, 0);
    CP_COMMIT();
    const int mb = wm * 32, nb = wn * 64;

    for (int ks = 0; ks < 12; ks++) {
        const int buf = ks & 1;
        if (ks < 11) { load_tiles(ks + 1, buf ^ 1); CP_COMMIT(); CP_WAIT(1); }
        else         { CP_WAIT(0); }
        __syncthreads();
        const unsigned as_u = smem_u32(As[buf]);
        const unsigned bs_u = smem_u32(Bs[buf]);
#pragma unroll
        for (int kk = 0; kk < 32; kk += 16) {
            unsigned a[2][4];
#pragma unroll
            for (int mf = 0; mf < 2; mf++) {
                unsigned ah = (mb + mf * 16 + (g8 & 1) * 8 + r8) * AS_STR_M
                            + kk + (g8 >> 1) * 8;
                ldmat4(a[mf], as_u + ah * 2);
            }
#pragma unroll
            for (int ng = 0; ng < 4; ng++) {
                unsigned bh = (kk + (g8 & 1) * 8 + r8) * BS_STR
                            + nb + ng * 16 + (g8 >> 1) * 8;
                unsigned bq[4];
                ldmat4t(bq, bs_u + bh * 2);
#pragma unroll
                for (int mf = 0; mf < 2; mf++) {
                    mma_f16(c[mf][ng * 2 + 0], a[mf], bq[0], bq[1]);
                    mma_f16(c[mf][ng * 2 + 1], a[mf], bq[2], bq[3]);
                }
            }
        }
        __syncthreads();
    }

    float2 brow[8];
#pragma unroll
    for (int nf = 0; nf < 8; nf++)
        brow[nf] = *(const float2*)(bias + n0 + nb + nf * 8 + qd * 2);
#pragma unroll
    for (int mf = 0; mf < 2; mf++) {
#pragma unroll
        for (int half = 0; half < 2; half++) {
            int m = m0 + mb + mf * 16 + grp + half * 8;
            if (m < NPIX) {
                float* cp = Cb + (size_t)m * NC + n0 + nb + qd * 2;
#pragma unroll
                for (int nf = 0; nf < 8; nf++) {
                    float2 v;
                    v.x = c[mf][nf][half * 2 + 0] + brow[nf].x;
                    v.y = c[mf][nf][half * 2 + 1] + brow[nf].y;
                    *(float2*)(cp + nf * 8) = v;
                }
            }
        }
    }
}

// ---------------------------------------------------------------------------
// K0: fp32 -> fp16 conversion
// ---------------------------------------------------------------------------
__global__ void f2h_kernel(const float4* __restrict__ src,
                           __half2* __restrict__ dst, long n4)
{
    long i = (long)blockIdx.x * blockDim.x + threadIdx.x;
    long stride = (long)gridDim.x * blockDim.x;
    for (; i < n4; i += stride) {
        float4 v = src[i];
        dst[2 * i]     = __floats2half2_rn(v.x, v.y);
        dst[2 * i + 1] = __floats2half2_rn(v.z, v.w);
    }
}

// ---------------------------------------------------------------------------
// K2: agent pooling — mean of q over 8x8 windows, pre-scaled, fp16.
// ---------------------------------------------------------------------------
__global__ void pool_kernel()
{
    const int ch = threadIdx.x;
    const int h = ch >> 5, d = ch & 31;
    const int a  = blockIdx.x;
    const int b  = blockIdx.y;
    const int py = a / 7, px = a % 7;
    const __half* src = g_qh + ((size_t)(b * NH + h) * NPIX) * 32 + d;
    float s = 0.f;
#pragma unroll
    for (int i = 0; i < 8; i++)
#pragma unroll
        for (int j = 0; j < 8; j++)
            s += __half2float(src[(size_t)((py * 8 + i) * HW + px * 8 + j) * 32]);
    g_agenth[((size_t)(b * NH + h) * 64 + a) * 32 + d] =
        __float2half_rn(s * (1.f / 64.f) * SCALE);
}

// ---------------------------------------------------------------------------
// K3a: bilinear upsample an_bias -> pb1 [h][a][n] fp32
// ---------------------------------------------------------------------------
__device__ __forceinline__ float bilin7(const float* t, int y, int x)
{
    float fy = (y + 0.5f) * 0.125f - 0.5f;
    fy = fminf(fmaxf(fy, 0.f), 6.f);
    int y0 = (int)fy; float wy = fy - (float)y0; int y1 = min(y0 + 1, 6);
    float fx = (x + 0.5f) * 0.125f - 0.5f;
    fx = fminf(fmaxf(fx, 0.f), 6.f);
    int x0 = (int)fx; float wx = fx - (float)x0; int x1 = min(x0 + 1, 6);
    return (1.f - wy) * ((1.f - wx) * t[y0 * 7 + x0] + wx * t[y0 * 7 + x1])
         +        wy  * ((1.f - wx) * t[y1 * 7 + x0] + wx * t[y1 * 7 + x1]);
}

__global__ void biasup_pb1(const float* __restrict__ an)
{
    int idx = blockIdx.x * 256 + threadIdx.x;    // < 12*49*3136
    int xy = idx % NPIX;
    int ha = idx / NPIX;
    g_pb1[idx] = bilin7(an + (size_t)ha * 49, xy / HW, xy % HW);
}

// K3b: na_bias -> ab1t [h][n][64] fp32, -1e30 padding for a >= 49
__global__ void biasup_ab1t(const float* __restrict__ na)
{
    int idx = blockIdx.x * 256 + threadIdx.x;    // < 12*3136*64
    int a = idx & 63;
    int rest = idx >> 6;
    int n = rest % NPIX;
    int h = rest / NPIX;
    float v = -1e30f;
    if (a < NA)
        v = bilin7(na + (size_t)(h * NA + a) * 49, n / HW, n % HW);
    g_ab1t[idx] = v;
}

// ---------------------------------------------------------------------------
// K4: stage 1 (mma) — AV[b,h,a,:] = softmax_n(ah_s·k_n + pb1) @ V
// grid (12, 32), block 128 (4 warps, 16 agent-rows each; rows 49-63 dummy)
// ---------------------------------------------------------------------------
__global__ void __launch_bounds__(128) stage1_mma()
{
    const int h = blockIdx.x, b = blockIdx.y;
    const int tid = threadIdx.x;
    const int warp = tid >> 5, lane = tid & 31;
    const int grp = lane >> 2, qd = lane & 3;
    const int g8 = lane >> 3, r8 = lane & 7;

    __shared__ __align__(16) __half ah_s[64 * 40];
    __shared__ __align__(16) __half Ks[2][64 * 40];
    __shared__ __align__(16) __half Vs[2][64 * 40];

    const size_t bh = (size_t)(b * NH + h);
    for (int e = tid; e < 256; e += 128) {
        int row = e >> 2, c4 = e & 3;
        *(uint4*)&ah_s[row * 40 + c4 * 8] =
            *(const uint4*)&g_agenth[(bh * 64 + row) * 32 + c4 * 8];
    }
    __syncthreads();

    unsigned af[2][4];
#pragma unroll
    for (int kk2 = 0; kk2 < 2; kk2++)
        ldmat4(af[kk2], smem_u32(&ah_s[(warp * 16 + (g8 & 1) * 8 + r8) * 40
                                       + kk2 * 16 + (g8 >> 1) * 8]));

    const __half* kb = g_kh + bh * NPIX * 32;
    const __half* vb = g_vh + bh * NPIX * 32;
    auto loadKV = [&](int c64, int buf) {
        const __half* kp = kb + (size_t)c64 * 64 * 32;
        const __half* vp = vb + (size_t)c64 * 64 * 32;
        for (int e = tid; e < 256; e += 128) {
            int row = e >> 2, c4 = e & 3;
            cp_async16(smem_u32(&Ks[buf][row * 40 + c4 * 8]), kp + row * 32 + c4 * 8);
            cp_async16(smem_u32(&Vs[buf][row * 40 + c4 * 8]), vp + row * 32 + c4 * 8);
        }
    };

    float av[4][4];
#pragma unroll
    for (int i = 0; i < 4; i++)
#pragma unroll
        for (int j = 0; j < 4; j++) av[i][j] = 0.f;
    float l0 = 0.f, l1 = 0.f;
    const int a_lo = warp * 16 + grp, a_hi = a_lo + 8;
    const float* pb_lo = g_pb1 + (size_t)(h * NA + a_lo) * NPIX;
    const float* pb_hi = g_pb1 + (size_t)(h * NA + a_hi) * NPIX;

    loadKV(0, 0);
    CP_COMMIT();

    for (int c = 0; c < 49; c++) {
        const int buf = c & 1;
        if (c < 48) { loadKV(c + 1, buf ^ 1); CP_COMMIT(); CP_WAIT(1); }
        else        { CP_WAIT(0); }
        __syncthreads();

        float s[8][4];
#pragma unroll
        for (int i = 0; i < 8; i++)
#pragma unroll
            for (int j = 0; j < 4; j++) s[i][j] = 0.f;

#pragma unroll
        for (int ng = 0; ng < 4; ng++) {
            unsigned base = smem_u32(&Ks[buf][(ng * 16 + (g8 >> 1) * 8 + r8) * 40
                                              + (g8 & 1) * 8]);
            unsigned bk0[4], bk1[4];
            ldmat4(bk0, base);
            ldmat4(bk1, base + 32);           // k 16..31 (+16 halves)
            mma_f16(s[2 * ng],     af[0], bk0[0], bk0[1]);
            mma_f16(s[2 * ng],     af[1], bk1[0], bk1[1]);
            mma_f16(s[2 * ng + 1], af[0], bk0[2], bk0[3]);
            mma_f16(s[2 * ng + 1], af[1], bk1[2], bk1[3]);
        }

        unsigned ph[8][2];
        const int nbase = c * 64;
#pragma unroll
        for (int nf = 0; nf < 8; nf++) {
            int n = nbase + nf * 8 + qd * 2;
            float2 blo = *(const float2*)(pb_lo + n);
            float2 bhi = *(const float2*)(pb_hi + n);
            float e0 = __expf(s[nf][0] + blo.x);
            float e1 = __expf(s[nf][1] + blo.y);
            float e2 = __expf(s[nf][2] + bhi.x);
            float e3 = __expf(s[nf][3] + bhi.y);
            l0 += e0 + e1; l1 += e2 + e3;
            ph[nf][0] = h2u(e0, e1);
            ph[nf][1] = h2u(e2, e3);
        }

#pragma unroll
        for (int kk = 0; kk < 4; kk++) {
            unsigned a2[4] = { ph[2 * kk][0], ph[2 * kk][1],
                               ph[2 * kk + 1][0], ph[2 * kk + 1][1] };
#pragma unroll
            for (int ng = 0; ng < 2; ng++) {
                unsigned bv[4];
                ldmat4t(bv, smem_u32(&Vs[buf][(kk * 16 + (g8 & 1) * 8 + r8) * 40
                                              + ng * 16 + (g8 >> 1) * 8]));
                mma_f16(av[2 * ng],     a2, bv[0], bv[1]);
                mma_f16(av[2 * ng + 1], a2, bv[2], bv[3]);
            }
        }
        __syncthreads();
    }

    l0 += __shfl_xor_sync(~0u, l0, 1); l0 += __shfl_xor_sync(~0u, l0, 2);
    l1 += __shfl_xor_sync(~0u, l1, 1); l1 += __shfl_xor_sync(~0u, l1, 2);
    float i0 = 1.f / l0, i1 = 1.f / l1;
#pragma unroll
    for (int nf = 0; nf < 4; nf++) {
        int d = nf * 8 + qd * 2;
        __half2 lo = (a_lo < NA)
            ? __floats2half2_rn(av[nf][0] * i0, av[nf][1] * i0)
            : __floats2half2_rn(0.f, 0.f);
        __half2 hi = (a_hi < NA)
            ? __floats2half2_rn(av[nf][2] * i1, av[nf][3] * i1)
            : __floats2half2_rn(0.f, 0.f);
        *(__half2*)&g_avh[(bh * 64 + a_lo) * 32 + d] = lo;
        *(__half2*)&g_avh[(bh * 64 + a_hi) * 32 + d] = hi;
    }
}

// ---------------------------------------------------------------------------
// K5: stage 2 (mma) — o = softmax_a(q·ah_s + ab1t) @ AV, fp16 out
// grid (25, 12, 32), block 128 (4 warps, 32 query-rows each)
// ---------------------------------------------------------------------------
__global__ void __launch_bounds__(128) stage2_mma()
{
    const int n0 = blockIdx.x * 128;
    const int h = blockIdx.y, b = blockIdx.z;
    const int tid = threadIdx.x;
    const int warp = tid >> 5, lane = tid & 31;
    const int grp = lane >> 2, qd = lane & 3;
    const int g8 = lane >> 3, r8 = lane & 7;

    __shared__ __align__(16) __half q_s[128 * 40];
    __shared__ __align__(16) __half a_s[64 * 40];
    __shared__ __align__(16) __half v_s[64 * 40];

    const size_t bh = (size_t)(b * NH + h);
    const __half* qp = g_qh + (bh * NPIX + n0) * 32;
    for (int e = tid; e < 512; e += 128) {
        int row = e >> 2, c4 = e & 3;
        *(uint4*)&q_s[row * 40 + c4 * 8] = *(const uint4*)&qp[row * 32 + c4 * 8];
    }
    for (int e = tid; e < 256; e += 128) {
        int row = e >> 2, c4 = e & 3;
        *(uint4*)&a_s[row * 40 + c4 * 8] =
            *(const uint4*)&g_agenth[(bh * 64 + row) * 32 + c4 * 8];
        *(uint4*)&v_s[row * 40 + c4 * 8] =
            *(const uint4*)&g_avh[(bh * 64 + row) * 32 + c4 * 8];
    }
    __syncthreads();

    unsigned aq[2][2][4];
#pragma unroll
    for (int mf = 0; mf < 2; mf++)
#pragma unroll
        for (int kk2 = 0; kk2 < 2; kk2++)
            ldmat4(aq[mf][kk2],
                   smem_u32(&q_s[(warp * 32 + mf * 16 + (g8 & 1) * 8 + r8) * 40
                                 + kk2 * 16 + (g8 >> 1) * 8]));

    float s[2][8][4];
#pragma unroll
    for (int mf = 0; mf < 2; mf++)
#pragma unroll
        for (int i = 0; i < 8; i++)
#pragma unroll
            for (int j = 0; j < 4; j++) s[mf][i][j] = 0.f;

#pragma unroll
    for (int ng = 0; ng < 4; ng++) {
        unsigned base = smem_u32(&a_s[(ng * 16 + (g8 >> 1) * 8 + r8) * 40
                                      + (g8 & 1) * 8]);
        unsigned bk0[4], bk1[4];
        ldmat4(bk0, base);
        ldmat4(bk1, base + 32);
#pragma unroll
        for (int mf = 0; mf < 2; mf++) {
            mma_f16(s[mf][2 * ng],     aq[mf][0], bk0[0], bk0[1]);
            mma_f16(s[mf][2 * ng],     aq[mf][1], bk1[0], bk1[1]);
            mma_f16(s[mf][2 * ng + 1], aq[mf][0], bk0[2], bk0[3]);
            mma_f16(s[mf][2 * ng + 1], aq[mf][1], bk1[2], bk1[3]);
        }
    }

    float l[2][2] = {{0.f, 0.f}, {0.f, 0.f}};
    unsigned ph[2][8][2];
#pragma unroll
    for (int mf = 0; mf < 2; mf++) {
        int r_lo = n0 + warp * 32 + mf * 16 + grp;
        const float* ab_lo = g_ab1t + ((size_t)h * NPIX + r_lo) * 64;
        const float* ab_hi = ab_lo + 8 * 64;
#pragma unroll
        for (int nf = 0; nf < 8; nf++) {
            int col = nf * 8 + qd * 2;
            float2 tlo = *(const float2*)(ab_lo + col);
            float2 thi = *(const float2*)(ab_hi + col);
            float e0 = __expf(s[mf][nf][0] + tlo.x);
            float e1 = __expf(s[mf][nf][1] + tlo.y);
            float e2 = __expf(s[mf][nf][2] + thi.x);
            float e3 = __expf(s[mf][nf][3] + thi.y);
            l[mf][0] += e0 + e1; l[mf][1] += e2 + e3;
            ph[mf][nf][0] = h2u(e0, e1);
            ph[mf][nf][1] = h2u(e2, e3);
        }
    }

    float o[2][4][4];
#pragma unroll
    for (int mf = 0; mf < 2; mf++)
#pragma unroll
        for (int i = 0; i < 4; i++)
#pragma unroll
            for (int j = 0; j < 4; j++) o[mf][i][j] = 0.f;

#pragma unroll
    for (int kk = 0; kk < 4; kk++) {
        unsigned a2[2][4];
#pragma unroll
        for (int mf = 0; mf < 2; mf++) {
            a2[mf][0] = ph[mf][2 * kk][0];
            a2[mf][1] = ph[mf][2 * kk][1];
            a2[mf][2] = ph[mf][2 * kk + 1][0];
            a2[mf][3] = ph[mf][2 * kk + 1][1];
        }
#pragma unroll
        for (int ng = 0; ng < 2; ng++) {
            unsigned bv[4];
            ldmat4t(bv, smem_u32(&v_s[(kk * 16 + (g8 & 1) * 8 + r8) * 40
                                      + ng * 16 + (g8 >> 1) * 8]));
#pragma unroll
            for (int mf = 0; mf < 2; mf++) {
                mma_f16(o[mf][2 * ng],     a2[mf], bv[0], bv[1]);
                mma_f16(o[mf][2 * ng + 1], a2[mf], bv[2], bv[3]);
            }
        }
    }

#pragma unroll
    for (int mf = 0; mf < 2; mf++) {
        float la = l[mf][0], lb = l[mf][1];
        la += __shfl_xor_sync(~0u, la, 1); la += __shfl_xor_sync(~0u, la, 2);
        lb += __shfl_xor_sync(~0u, lb, 1); lb += __shfl_xor_sync(~0u, lb, 2);
        float i0 = 1.f / la, i1 = 1.f / lb;
        int m_lo = n0 + warp * 32 + mf * 16 + grp;
        int m_hi = m_lo + 8;
#pragma unroll
        for (int nf = 0; nf < 4; nf++) {
            int d = nf * 8 + qd * 2;
            if (m_lo < NPIX)
                *(__half2*)&g_oh[((size_t)b * NPIX + m_lo) * NC + h * 32 + d] =
                    __floats2half2_rn(o[mf][nf][0] * i0, o[mf][nf][1] * i0);
            if (m_hi < NPIX)
                *(__half2*)&g_oh[((size_t)b * NPIX + m_hi) * NC + h * 32 + d] =
                    __floats2half2_rn(o[mf][nf][2] * i1, o[mf][nf][3] * i1);
        }
    }
}

// ---------------------------------------------------------------------------
// K6: depthwise 3x3 conv on v (fp16), RMW-add into g_oh.
// ---------------------------------------------------------------------------
__global__ void dwc_kernel(const float* __restrict__ dwc_w,
                           const float* __restrict__ dwc_b)
{
    const int ch = threadIdx.x;
    const int hh = ch >> 5, d = ch & 31;
    const int nn = blockIdx.x;
    const int b  = blockIdx.y;
    const int y = nn / HW, x = nn % HW;
    const __half* vb = g_vh + ((size_t)(b * NH + hh) * NPIX) * 32 + d;

    float s = dwc_b[ch];
#pragma unroll
    for (int dy = -1; dy <= 1; dy++)
#pragma unroll
        for (int dx = -1; dx <= 1; dx++) {
            int yy = y + dy, xx = x + dx;
            if (yy >= 0 && yy < HW && xx >= 0 && xx < HW)
                s += __half2float(vb[(size_t)(yy * HW + xx) * 32])
                   * dwc_w[ch * 9 + (dy + 1) * 3 + (dx + 1)];
        }
    size_t idx = (size_t)(b * NPIX + nn) * NC + ch;
    g_oh[idx] = __float2half_rn(__half2float(g_oh[idx]) + s);
}

// ---------------------------------------------------------------------------
// K8: out[b][ch][nn] = x[b][ch][nn] * sigmoid(oproj[b][nn][ch])
// ---------------------------------------------------------------------------
__global__ void final_kernel(const float* __restrict__ x,
                             float* __restrict__ out)
{
    __shared__ float tile[32][33];
    const int b   = blockIdx.z;
    const int ch0 = blockIdx.y * 32;
    const int nn0 = blockIdx.x * 32;
    const int tx = threadIdx.x, ty = threadIdx.y;

#pragma unroll
    for (int k = 0; k < 4; k++) {
        int r = ty + k * 8;
        tile[r][tx] = g_oproj[(size_t)(b * NPIX + nn0 + r) * NC + ch0 + tx];
    }
    __syncthreads();
#pragma unroll
    for (int k = 0; k < 4; k++) {
        int r = ty + k * 8;
        size_t idx = ((size_t)b * NC + ch0 + r) * NPIX + nn0 + tx;
        float o = tile[tx][r];
        out[idx] = x[idx] * (1.f / (1.f + __expf(-o)));
    }
}

// ---------------------------------------------------------------------------
extern "C" void kernel_launch(void* const* d_in, const int* in_sizes, int n_in,
                              void* d_out, int out_size)
{
    (void)in_sizes; (void)n_in; (void)out_size;
    const float* x      = (const float*)d_in[0];
    const float* qkv_w  = (const float*)d_in[1];
    const float* qkv_b  = (const float*)d_in[2];
    const float* proj_w = (const float*)d_in[3];
    const float* proj_b = (const float*)d_in[4];
    const float* an_b   = (const float*)d_in[5];
    const float* na_b   = (const float*)d_in[6];
    const float* dwc_w  = (const float*)d_in[7];
    const float* dwc_b  = (const float*)d_in[8];
    float* out = (float*)d_out;

    __half* xh;      cudaGetSymbolAddress((void**)&xh,      g_xh);
    __half* wqkvh;   cudaGetSymbolAddress((void**)&wqkvh,   g_wqkvh);
    __half* wprojh;  cudaGetSymbolAddress((void**)&wprojh,  g_wprojh);
    __half* oh;      cudaGetSymbolAddress((void**)&oh,      g_oh);
    float* proj_out; cudaGetSymbolAddress((void**)&proj_out, g_oproj);

    // 0. fp32 -> fp16 conversions
    f2h_kernel<<<2048, 256>>>((const float4*)x, (__half2*)xh,
                              (long)NB * NC * NPIX / 4);
    f2h_kernel<<<128, 256>>>((const float4*)qkv_w, (__half2*)wqkvh,
                             (long)NC * NQKV / 4);
    f2h_kernel<<<64, 256>>>((const float4*)proj_w, (__half2*)wprojh,
                            (long)NC * NC / 4);

    // 1. qkv GEMM -> fp16 head-split q/k/v
    gemm_qkv<<<dim3(25, 9, 32), 256>>>(xh, wqkvh, qkv_b);
    // 2. agent tokens (pre-scaled fp16)
    pool_kernel<<<dim3(49, 32), 384>>>();
    // 3. bias upsamples
    biasup_pb1<<<7203, 256>>>(an_b);
    biasup_ab1t<<<9408, 256>>>(na_b);
    // 4. stage 1 (mma)
    stage1_mma<<<dim3(12, 32), 128>>>();
    // 5. stage 2 (mma) -> g_oh fp16
    stage2_mma<<<dim3(25, 12, 32), 128>>>();
    // 6. depthwise conv on v, RMW into g_oh
    dwc_kernel<<<dim3(3136, 32), 384>>>(dwc_w, dwc_b);
    // 7. proj GEMM -> g_oproj fp32
    gemm_proj<<<dim3(25, 3, 32), 256>>>(oh, wprojh, proj_b, proj_out);
    // 8. transpose + sigmoid gate
    final_kernel<<<dim3(98, 12, 32), dim3(32, 8)>>>(x, out);
}